// round 1
// baseline (speedup 1.0000x reference)
#include <cuda_runtime.h>
#include <math.h>

// ---------------- problem constants ----------------
constexpr int   B_TOT  = 1000000;
constexpr int   SPIN   = 1000;
constexpr int   TRAIN  = 800000;
constexpr float ML     = 2.9086f;
constexpr float SL     = 1.898f;
constexpr float U1MAX  = 221.519f;

// chunked-scan parameters
constexpr int CHUNK  = 128;   // elements per chunk (multiple of 32)
constexpr int WARM   = 384;   // burn-in steps (contraction <= ~0.95 => err ~1e-9)
constexpr int NCH    = (B_TOT + CHUNK - 1) / CHUNK;        // 7813
constexpr int NCH_PAD = ((NCH + 31) / 32) * 32;            // 7840 (whole warps)

// ---------------- reduction accumulators ----------------
__device__ double g_sum;
__device__ double g_sumsq;
__device__ float  g_obsstd;

// ---------------- shared step math ----------------
struct P {
    float mo, inv_so;
    float oo1, ol1;
    float b0_yom, w1o;
    float b0_ylm, w2l;
    float w1u, b0_yum;
};

__device__ __forceinline__ float sigm(float z) {
    return __fdividef(1.0f, 1.0f + __expf(-z));
}

// one recurrence step: returns updated c (state only)
__device__ __forceinline__ float step_c(float c, float u1, float u2, const P& p) {
    float cn  = (c - p.mo) * p.inv_so;
    float ib  = sigm(p.b0_yum + (cn + u1 * (1.0f / U1MAX)) * p.w1u);
    float oo  = p.oo1 * sigm(p.b0_yom + cn * p.w1o);
    float ol  = p.ol1 * sigm(p.b0_ylm + ((u2 - ML) / SL) * p.w2l);
    float olc = (c > 0.0f) ? fminf(ol, __fdividef(u2, c)) : ol;
    float f   = 1.0f - oo - olc;
    return f * c + (1.0f - ib) * u1;
}

__device__ __forceinline__ P load_params(
    const float* cmean, const float* cstd,
    const float* wro, const float* wrl, const float* wrf,
    const float* b0o, const float* wb1o,
    const float* b0l, const float* wb2l,
    const float* wb1u, const float* b0u)
{
    P p;
    p.mo     = cmean[0];
    p.inv_so = 1.0f / cstd[0];
    float eo = __expf(wro[0]);
    float el = __expf(wrl[0]);
    float ef = __expf(wrf[0]);
    float id = __fdividef(1.0f, eo + el + ef);
    p.oo1    = eo * id;
    p.ol1    = el * id;
    p.b0_yom = b0o[0];  p.w1o = wb1o[0];
    p.b0_ylm = b0l[0];  p.w2l = wb2l[0];
    p.w1u    = wb1u[0]; p.b0_yum = b0u[0];
    return p;
}

// ---------------- kernel: zero accumulators ----------------
__global__ void zero_k() { g_sum = 0.0; g_sumsq = 0.0; }

// ---------------- kernel: sum / sumsq over y_obs[SPIN:TRAIN] ----------------
__global__ void reduce_k(const float* __restrict__ y) {
    double s = 0.0, s2 = 0.0;
    int stride = gridDim.x * blockDim.x;
    for (int i = SPIN + blockIdx.x * blockDim.x + threadIdx.x; i < TRAIN; i += stride) {
        double v = (double)y[i];
        s  += v;
        s2 += v * v;
    }
    #pragma unroll
    for (int o = 16; o > 0; o >>= 1) {
        s  += __shfl_down_sync(0xffffffffu, s,  o);
        s2 += __shfl_down_sync(0xffffffffu, s2, o);
    }
    if ((threadIdx.x & 31) == 0) {
        atomicAdd(&g_sum, s);
        atomicAdd(&g_sumsq, s2);
    }
}

// ---------------- kernel: finalize std (ddof=1) ----------------
__global__ void finalize_k() {
    double n   = (double)(TRAIN - SPIN);
    double var = (g_sumsq - g_sum * g_sum / n) / (n - 1.0);
    g_obsstd   = (float)sqrt(var);
}

// ---------------- kernel: chunked scan (phase 1) ----------------
// Each thread owns one chunk of CHUNK steps; burns in WARM steps from c=0.
// The c-trajectory (pre-update state at each t) is written coalesced into
// c_out[t] via a 32x32 SMEM transpose per warp.
__global__ __launch_bounds__(64) void scan_k(
    const float2* __restrict__ x,
    float* __restrict__ c_out,
    const float* cmean, const float* cstd,
    const float* wro, const float* wrl, const float* wrf,
    const float* b0o, const float* wb1o,
    const float* b0l, const float* wb2l,
    const float* wb1u, const float* b0u)
{
    __shared__ float tile[2][32][33];   // [warp][lane=chunk-in-warp][step-in-tile]

    const int lane = threadIdx.x & 31;
    const int warp = threadIdx.x >> 5;
    const int chunk = blockIdx.x * blockDim.x + threadIdx.x;
    const int warp_chunk0 = chunk - lane;

    const P p = load_params(cmean, cstd, wro, wrl, wrf, b0o, wb1o, b0l, wb2l, wb1u, b0u);

    const int start  = chunk * CHUNK;
    const bool active = (chunk < NCH) && (start < B_TOT);
    const int end    = active ? min(start + CHUNK, B_TOT) : start;

    float c = 0.0f;
    if (active) {
        int ws = start - WARM;
        if (ws < 0) ws = 0;
        #pragma unroll 4
        for (int t = ws; t < start; ++t) {
            float2 u = x[t];
            c = step_c(c, u.x, u.y, p);
        }
    }

    #pragma unroll
    for (int ti = 0; ti < CHUNK / 32; ++ti) {
        int t0 = start + ti * 32;
        if (active && t0 < end) {
            #pragma unroll 4
            for (int s = 0; s < 32; ++s) {
                float2 u = x[t0 + s];
                tile[warp][lane][s] = c;      // state BEFORE update = c[t]
                c = step_c(c, u.x, u.y, p);
            }
        }
        __syncwarp();
        // coalesced write: row r is chunk (warp_chunk0 + r), cols are steps
        #pragma unroll 4
        for (int r = 0; r < 32; ++r) {
            int idx = (warp_chunk0 + r) * CHUNK + ti * 32 + lane;
            if (idx < B_TOT)
                c_out[idx] = tile[warp][r][lane];
        }
        __syncwarp();
    }
}

// ---------------- kernel: pointwise outputs (phase 2) ----------------
__global__ __launch_bounds__(256) void point_k(
    const float2* __restrict__ x,
    float* __restrict__ out,
    const int* __restrict__ time_lag_p,
    const float* cmean, const float* cstd,
    const float* wro, const float* wrl, const float* wrf,
    const float* b0o, const float* wb1o,
    const float* b0l, const float* wb2l,
    const float* wb1u, const float* b0u)
{
    int t = blockIdx.x * blockDim.x + threadIdx.x;
    if (t >= B_TOT) return;

    const P p = load_params(cmean, cstd, wro, wrl, wrf, b0o, wb1o, b0l, wb2l, wb1u, b0u);
    const int   tl = time_lag_p[0];
    const float os = g_obsstd;

    float*       c_arr = out + (size_t)B_TOT;     // c written by phase 1
    float c = c_arr[t];
    float2 u = x[t];
    float u1 = u.x, u2 = u.y;

    float cn  = (c - p.mo) * p.inv_so;
    float ib  = sigm(p.b0_yum + (cn + u1 * (1.0f / U1MAX)) * p.w1u);
    float oo  = p.oo1 * sigm(p.b0_yom + cn * p.w1o);
    float ol  = p.ol1 * sigm(p.b0_ylm + ((u2 - ML) / SL) * p.w2l);
    float olc = (c > 0.0f) ? fminf(ol, __fdividef(u2, c)) : ol;
    float f   = 1.0f - oo - olc;

    float m   = (t >= tl) ? 1.0f : 0.0f;
    float bp  = ib * u1;
    float h   = oo * c + bp;

    const size_t B = (size_t)B_TOT;
    out[t]          = m * h;             // h_n
    out[B + t]      = m * c;             // c_n   (overwrites raw c — same value*mask)
    out[2 * B + t]  = m * (ol  * c);     // l_n
    out[3 * B + t]  = m * (olc * c);     // lc_n
    out[4 * B + t]  = m * bp;            // bp_n
    out[5 * B + t]  = m * ib;            // g_ib
    out[6 * B + t]  = m * oo;            // g_oo
    out[7 * B + t]  = m * ol;            // g_ol
    out[8 * B + t]  = m * olc;           // g_olc
    out[9 * B + t]  = m * f;             // g_f
    float2 hn;                           // h_nout = concat([h_n, obs_std], axis=1)
    hn.x = m * h;
    hn.y = m * os;
    reinterpret_cast<float2*>(out + 10 * B)[t] = hn;
    out[12 * B + t] = m * os;            // obs_std
}

// ---------------- launch ----------------
extern "C" void kernel_launch(void* const* d_in, const int* in_sizes, int n_in,
                              void* d_out, int out_size) {
    const float2* x     = (const float2*)d_in[0];
    const int*    tl    = (const int*)   d_in[2];
    const float*  y_obs = (const float*) d_in[3];
    const float*  cmean = (const float*) d_in[4];
    const float*  cstd  = (const float*) d_in[5];
    const float*  wro   = (const float*) d_in[6];
    const float*  wrl   = (const float*) d_in[7];
    const float*  wrf   = (const float*) d_in[8];
    const float*  b0o   = (const float*) d_in[9];
    const float*  wb1o  = (const float*) d_in[10];
    const float*  b0l   = (const float*) d_in[11];
    const float*  wb2l  = (const float*) d_in[12];
    const float*  wb1u  = (const float*) d_in[13];
    const float*  b0u   = (const float*) d_in[14];
    float* out = (float*)d_out;

    zero_k<<<1, 1>>>();
    reduce_k<<<256, 256>>>(y_obs);
    finalize_k<<<1, 1>>>();

    float* c_out = out + (size_t)B_TOT;  // stash raw c trajectory in c_n slot
    scan_k<<<(NCH_PAD + 63) / 64, 64>>>(x, c_out,
        cmean, cstd, wro, wrl, wrf, b0o, wb1o, b0l, wb2l, wb1u, b0u);

    point_k<<<(B_TOT + 255) / 256, 256>>>(x, out, tl,
        cmean, cstd, wro, wrl, wrf, b0o, wb1o, b0l, wb2l, wb1u, b0u);
}

// round 2
// speedup vs baseline: 2.2615x; 2.2615x over previous
#include <cuda_runtime.h>
#include <math.h>

// ---------------- problem constants ----------------
constexpr int   B_TOT  = 1000000;
constexpr int   SPIN   = 1000;
constexpr int   TRAIN  = 800000;
constexpr float ML     = 2.9086f;
constexpr float SL     = 1.898f;
constexpr float U1MAX  = 221.519f;

// chunked-scan parameters
constexpr int CHUNK   = 32;                         // steps per chunk
constexpr int WARMCH  = 8;                          // warm-up chunks (256 steps)
constexpr int NCH     = B_TOT / CHUNK;              // 31250 (exact)
constexpr int NCHPAD  = ((NCH + 31) / 32) * 32;     // 31264

// ---------------- device scratch (static: no allocation) ----------------
__device__ float2 g_xT[32 * NCHPAD];                // transposed input, ~8MB

constexpr int RBLOCKS = 132;
__device__ double g_part[RBLOCKS][2];
__device__ float  g_obsstd;

// ---------------- math helpers ----------------
__device__ __forceinline__ float tanha(float z) {
    float r;
    asm("tanh.approx.f32 %0, %1;" : "=f"(r) : "f"(z));
    return r;
}

struct P {
    float koo, coo;     // oo tanh-arg:  0.5*(b0_yom + w1o*cn)
    float kib, cib, kibu;
    float kol, col;
    float hoo1, hol1;   // 0.5*oo1, 0.5*ol1
    float mo, inv_so;
};

__device__ __forceinline__ P load_params(
    const float* cmean, const float* cstd,
    const float* wro, const float* wrl, const float* wrf,
    const float* b0o, const float* wb1o,
    const float* b0l, const float* wb2l,
    const float* wb1u, const float* b0u)
{
    P p;
    float mo = cmean[0];
    float inv_so = 1.0f / cstd[0];
    float eo = __expf(wro[0]);
    float el = __expf(wrl[0]);
    float ef = __expf(wrf[0]);
    float id = __fdividef(1.0f, eo + el + ef);
    p.hoo1 = 0.5f * eo * id;
    p.hol1 = 0.5f * el * id;
    float w1o = wb1o[0], w1u = wb1u[0], w2l = wb2l[0];
    p.koo  = 0.5f * w1o * inv_so;
    p.coo  = 0.5f * (b0o[0] - mo * inv_so * w1o);
    p.kib  = 0.5f * w1u * inv_so;
    p.cib  = 0.5f * (b0u[0] - mo * inv_so * w1u);
    p.kibu = 0.5f * w1u / U1MAX;
    p.kol  = 0.5f * w2l / SL;
    p.col  = 0.5f * (b0l[0] - (ML / SL) * w2l);
    p.mo = mo; p.inv_so = inv_so;
    return p;
}

// one recurrence step (state-only). sigmoid(z) = 0.5*tanh(z/2)+0.5.
// uses min(ol, u2/c)*c == min(ol*c, u2) for c>0 — no divide on the chain.
__device__ __forceinline__ float step_c(float c, float u1, float u2, const P& p) {
    float zo = fmaf(c, p.koo, p.coo);
    float zi = fmaf(c, p.kib, fmaf(u1, p.kibu, p.cib));
    float zl = fmaf(u2, p.kol, p.col);
    float oo = fmaf(tanha(zo), p.hoo1, p.hoo1);
    float ib = fmaf(tanha(zi), 0.5f, 0.5f);
    float ol = fmaf(tanha(zl), p.hol1, p.hol1);
    float olc_c = ol * c;
    float L  = (c > 0.0f) ? fminf(olc_c, u2) : olc_c;
    return (fmaf(-oo, c, c) - L) + fmaf(-ib, u1, u1);
}

// ---------------- kernel: sum/sumsq partials over y_obs[SPIN:TRAIN] ------
__global__ __launch_bounds__(256) void reduce_k(const float* __restrict__ y) {
    // [SPIN, TRAIN) = 799000 floats; SPIN*4 bytes is 16B aligned, count % 4 == 0
    const float4* y4 = reinterpret_cast<const float4*>(y + SPIN);
    const int n4 = (TRAIN - SPIN) / 4;
    double s = 0.0, s2 = 0.0;
    int stride = gridDim.x * blockDim.x;
    for (int i = blockIdx.x * blockDim.x + threadIdx.x; i < n4; i += stride) {
        float4 v = y4[i];
        double a = v.x, b = v.y, cc = v.z, d = v.w;
        s  += (a + b) + (cc + d);
        s2 += (a * a + b * b) + (cc * cc + d * d);
    }
    #pragma unroll
    for (int o = 16; o > 0; o >>= 1) {
        s  += __shfl_down_sync(0xffffffffu, s,  o);
        s2 += __shfl_down_sync(0xffffffffu, s2, o);
    }
    __shared__ double sh[2][8];
    int lane = threadIdx.x & 31, warp = threadIdx.x >> 5;
    if (lane == 0) { sh[0][warp] = s; sh[1][warp] = s2; }
    __syncthreads();
    if (warp == 0) {
        s  = (lane < 8) ? sh[0][lane] : 0.0;
        s2 = (lane < 8) ? sh[1][lane] : 0.0;
        #pragma unroll
        for (int o = 4; o > 0; o >>= 1) {
            s  += __shfl_down_sync(0xffffffffu, s,  o);
            s2 += __shfl_down_sync(0xffffffffu, s2, o);
        }
        if (lane == 0) { g_part[blockIdx.x][0] = s; g_part[blockIdx.x][1] = s2; }
    }
}

__global__ void finalize_k() {
    int lane = threadIdx.x;                 // 32 threads
    double s = 0.0, s2 = 0.0;
    for (int i = lane; i < RBLOCKS; i += 32) { s += g_part[i][0]; s2 += g_part[i][1]; }
    #pragma unroll
    for (int o = 16; o > 0; o >>= 1) {
        s  += __shfl_down_sync(0xffffffffu, s,  o);
        s2 += __shfl_down_sync(0xffffffffu, s2, o);
    }
    if (lane == 0) {
        double n = (double)(TRAIN - SPIN);
        g_obsstd = (float)sqrt((s2 - s * s / n) / (n - 1.0));
    }
}

// ---------------- kernel: transpose x -> xT[s][chunk] --------------------
__global__ __launch_bounds__(128) void transpose_k(const float2* __restrict__ x) {
    __shared__ float2 tile[4][32][33];
    const int lane = threadIdx.x & 31;
    const int warp = threadIdx.x >> 5;
    const int c0 = (blockIdx.x * 4 + warp) * 32;     // first chunk of this tile
    if (c0 >= NCH) return;
    #pragma unroll 4
    for (int i = 0; i < 32; ++i) {                   // read coalesced: t contiguous
        int ch = c0 + i;
        if (ch < NCH) tile[warp][i][lane] = x[ch * 32 + lane];
    }
    __syncwarp();
    #pragma unroll 4
    for (int s = 0; s < 32; ++s) {                   // write coalesced over chunk
        int ch = c0 + lane;
        if (ch < NCH) g_xT[s * NCHPAD + ch] = tile[warp][lane][s];
    }
}

// ---------------- kernel: chunked scan (phase 1) --------------------------
// Thread = one 32-step chunk; burns in WARMCH chunks from c=0 reading the
// transposed input (coalesced). Writes the c-trajectory to c_out[t] in
// natural layout via per-warp SMEM transpose (coalesced).
__global__ __launch_bounds__(256) void scan_k(
    float* __restrict__ c_out,
    const float* cmean, const float* cstd,
    const float* wro, const float* wrl, const float* wrf,
    const float* b0o, const float* wb1o,
    const float* b0l, const float* wb2l,
    const float* wb1u, const float* b0u)
{
    __shared__ float tile[8][32][33];
    const int lane = threadIdx.x & 31;
    const int warp = threadIdx.x >> 5;
    const int chunk = blockIdx.x * blockDim.x + threadIdx.x;
    const bool act = (chunk < NCH);

    const P p = load_params(cmean, cstd, wro, wrl, wrf, b0o, wb1o, b0l, wb2l, wb1u, b0u);

    float c = 0.0f;
    if (act) {
        // warm-up: replay chunks [chunk-WARMCH, chunk) — warp-uniform loop bounds
        #pragma unroll
        for (int d = WARMCH; d >= 1; --d) {
            int j = chunk - d;
            if (j >= 0) {
                #pragma unroll 8
                for (int s = 0; s < 32; ++s) {
                    float2 u = g_xT[s * NCHPAD + j];
                    c = step_c(c, u.x, u.y, p);
                }
            }
        }
        // main chunk: record pre-update state c[t]
        #pragma unroll 8
        for (int s = 0; s < 32; ++s) {
            tile[warp][lane][s] = c;
            float2 u = g_xT[s * NCHPAD + chunk];
            c = step_c(c, u.x, u.y, p);
        }
    }
    __syncwarp();
    const int w0 = blockIdx.x * blockDim.x + warp * 32;   // warp's first chunk
    #pragma unroll 4
    for (int r = 0; r < 32; ++r) {
        int ch = w0 + r;
        if (ch < NCH) c_out[ch * 32 + lane] = tile[warp][r][lane];
    }
}

// ---------------- kernel: pointwise outputs (phase 2) ---------------------
__global__ __launch_bounds__(256) void point_k(
    const float2* __restrict__ x,
    float* __restrict__ out,
    const int* __restrict__ time_lag_p,
    const float* cmean, const float* cstd,
    const float* wro, const float* wrl, const float* wrf,
    const float* b0o, const float* wb1o,
    const float* b0l, const float* wb2l,
    const float* wb1u, const float* b0u)
{
    int t = blockIdx.x * blockDim.x + threadIdx.x;
    if (t >= B_TOT) return;

    const P p = load_params(cmean, cstd, wro, wrl, wrf, b0o, wb1o, b0l, wb2l, wb1u, b0u);
    const int   tl = time_lag_p[0];
    const float os = g_obsstd;

    const size_t B = (size_t)B_TOT;
    float c = out[B + t];                 // raw c written by scan_k
    float2 u = x[t];
    float u1 = u.x, u2 = u.y;

    float zo = fmaf(c, p.koo, p.coo);
    float zi = fmaf(c, p.kib, fmaf(u1, p.kibu, p.cib));
    float zl = fmaf(u2, p.kol, p.col);
    float oo = fmaf(tanha(zo), p.hoo1, p.hoo1);
    float ib = fmaf(tanha(zi), 0.5f, 0.5f);
    float ol = fmaf(tanha(zl), p.hol1, p.hol1);
    float olc = (c > 0.0f) ? fminf(ol, __fdividef(u2, c)) : ol;
    float f   = 1.0f - oo - olc;

    float m  = (t >= tl) ? 1.0f : 0.0f;
    float bp = ib * u1;
    float h  = fmaf(oo, c, bp);

    out[t]          = m * h;              // h_n
    out[B + t]      = m * c;              // c_n (same-address read->write, safe)
    out[2 * B + t]  = m * (ol  * c);      // l_n
    out[3 * B + t]  = m * (olc * c);      // lc_n
    out[4 * B + t]  = m * bp;             // bp_n
    out[5 * B + t]  = m * ib;             // g_ib
    out[6 * B + t]  = m * oo;             // g_oo
    out[7 * B + t]  = m * ol;             // g_ol
    out[8 * B + t]  = m * olc;            // g_olc
    out[9 * B + t]  = m * f;              // g_f
    float2 hn;                            // h_nout = concat([h_n, obs_std], 1)
    hn.x = m * h;
    hn.y = m * os;
    reinterpret_cast<float2*>(out + 10 * B)[t] = hn;
    out[12 * B + t] = m * os;             // obs_std
}

// ---------------- launch ----------------
extern "C" void kernel_launch(void* const* d_in, const int* in_sizes, int n_in,
                              void* d_out, int out_size) {
    const float2* x     = (const float2*)d_in[0];
    const int*    tl    = (const int*)   d_in[2];
    const float*  y_obs = (const float*) d_in[3];
    const float*  cmean = (const float*) d_in[4];
    const float*  cstd  = (const float*) d_in[5];
    const float*  wro   = (const float*) d_in[6];
    const float*  wrl   = (const float*) d_in[7];
    const float*  wrf   = (const float*) d_in[8];
    const float*  b0o   = (const float*) d_in[9];
    const float*  wb1o  = (const float*) d_in[10];
    const float*  b0l   = (const float*) d_in[11];
    const float*  wb2l  = (const float*) d_in[12];
    const float*  wb1u  = (const float*) d_in[13];
    const float*  b0u   = (const float*) d_in[14];
    float* out = (float*)d_out;

    reduce_k<<<RBLOCKS, 256>>>(y_obs);
    finalize_k<<<1, 32>>>();

    constexpr int NTILES = (NCH + 31) / 32;               // 977
    transpose_k<<<(NTILES + 3) / 4, 128>>>(x);

    float* c_out = out + (size_t)B_TOT;                   // stash c in c_n slot
    scan_k<<<(NCHPAD + 255) / 256, 256>>>(c_out,
        cmean, cstd, wro, wrl, wrf, b0o, wb1o, b0l, wb2l, wb1u, b0u);

    point_k<<<(B_TOT + 255) / 256, 256>>>(x, out, tl,
        cmean, cstd, wro, wrl, wrf, b0o, wb1o, b0l, wb2l, wb1u, b0u);
}

// round 3
// speedup vs baseline: 2.3643x; 1.0455x over previous
#include <cuda_runtime.h>
#include <math.h>

// ---------------- problem constants ----------------
constexpr int   B_TOT  = 1000000;
constexpr int   SPIN   = 1000;
constexpr int   TRAIN  = 800000;
constexpr float ML     = 2.9086f;
constexpr float SL     = 1.898f;
constexpr float U1MAX  = 221.519f;

// chunked-scan parameters
constexpr int CHUNK   = 64;                   // steps per chunk
constexpr int WARMCH  = 2;                    // warm-up chunks (128 steps)
constexpr int NCH     = B_TOT / CHUNK;        // 15625 (exact)
constexpr int SCAN_BLK = 128;
constexpr int SCAN_GRID = (NCH + SCAN_BLK - 1) / SCAN_BLK;   // 123
constexpr int NCHPAD  = SCAN_GRID * SCAN_BLK;                // 15744

// ---------------- device scratch (static: no allocation) ----------------
__device__ float2 g_xT[CHUNK * NCHPAD];       // transposed input, ~8MB

constexpr int RBLOCKS = 132;
__device__ double g_part[RBLOCKS][2];
__device__ float  g_obsstd;

// ---------------- math helpers ----------------
__device__ __forceinline__ float tanha(float z) {
    float r;
    asm("tanh.approx.f32 %0, %1;" : "=f"(r) : "f"(z));
    return r;
}

struct P {
    float koo, coo;        // zo = koo*c + coo
    float kib, cib, kibu;  // zi = kib*c + (kibu*u1 + cib)
    float kol, col;        // zl = kol*u2 + col
    float hoo1, hol1;      // 0.5*oo1, 0.5*ol1
};

__device__ __forceinline__ P load_params(
    const float* cmean, const float* cstd,
    const float* wro, const float* wrl, const float* wrf,
    const float* b0o, const float* wb1o,
    const float* b0l, const float* wb2l,
    const float* wb1u, const float* b0u)
{
    P p;
    float mo = cmean[0];
    float inv_so = 1.0f / cstd[0];
    float eo = __expf(wro[0]);
    float el = __expf(wrl[0]);
    float ef = __expf(wrf[0]);
    float id = __fdividef(1.0f, eo + el + ef);
    p.hoo1 = 0.5f * eo * id;
    p.hol1 = 0.5f * el * id;
    float w1o = wb1o[0], w1u = wb1u[0], w2l = wb2l[0];
    p.koo  = 0.5f * w1o * inv_so;
    p.coo  = 0.5f * (b0o[0] - mo * inv_so * w1o);
    p.kib  = 0.5f * w1u * inv_so;
    p.cib  = 0.5f * (b0u[0] - mo * inv_so * w1u);
    p.kibu = 0.5f * w1u / U1MAX;
    p.kol  = 0.5f * w2l / SL;
    p.col  = 0.5f * (b0l[0] - (ML / SL) * w2l);
    return p;
}

// one recurrence step. sigmoid(z)=0.5*tanh(z/2)+0.5; min(ol,u2/c)*c == min(ol*c,u2).
// c' = [((c-hc)+hu1) - L] - hc*to - hu1*ti   (chain: fma->tanh->fma->fma ~ 28cyc)
__device__ __forceinline__ float step_c(float c, float u1, float u2, const P& p) {
    float hu1 = 0.5f * u1;                       // off-chain
    float zib = fmaf(u1, p.kibu, p.cib);         // off-chain
    float zl  = fmaf(u2, p.kol, p.col);          // off-chain
    float ol  = fmaf(tanha(zl), p.hol1, p.hol1); // off-chain MUFU
    float zo  = fmaf(c, p.koo, p.coo);
    float zi  = fmaf(c, p.kib, zib);
    float to  = tanha(zo);
    float ti  = tanha(zi);
    float hc  = p.hoo1 * c;                      // parallel with tanh
    float olc_c = ol * c;
    float L   = (c > 0.0f) ? fminf(olc_c, u2) : olc_c;
    float base = ((c - hc) + hu1) - L;           // parallel with tanh
    return fmaf(-hu1, ti, fmaf(-hc, to, base));
}

// ---------------- kernel: sum/sumsq partials over y_obs[SPIN:TRAIN] ------
__global__ __launch_bounds__(256) void reduce_k(const float* __restrict__ y) {
    const float4* y4 = reinterpret_cast<const float4*>(y + SPIN);
    const int n4 = (TRAIN - SPIN) / 4;
    double s = 0.0, s2 = 0.0;
    int stride = gridDim.x * blockDim.x;
    for (int i = blockIdx.x * blockDim.x + threadIdx.x; i < n4; i += stride) {
        float4 v = y4[i];
        double a = v.x, b = v.y, cc = v.z, d = v.w;
        s  += (a + b) + (cc + d);
        s2 += (a * a + b * b) + (cc * cc + d * d);
    }
    #pragma unroll
    for (int o = 16; o > 0; o >>= 1) {
        s  += __shfl_down_sync(0xffffffffu, s,  o);
        s2 += __shfl_down_sync(0xffffffffu, s2, o);
    }
    __shared__ double sh[2][8];
    int lane = threadIdx.x & 31, warp = threadIdx.x >> 5;
    if (lane == 0) { sh[0][warp] = s; sh[1][warp] = s2; }
    __syncthreads();
    if (warp == 0) {
        s  = (lane < 8) ? sh[0][lane] : 0.0;
        s2 = (lane < 8) ? sh[1][lane] : 0.0;
        #pragma unroll
        for (int o = 4; o > 0; o >>= 1) {
            s  += __shfl_down_sync(0xffffffffu, s,  o);
            s2 += __shfl_down_sync(0xffffffffu, s2, o);
        }
        if (lane == 0) { g_part[blockIdx.x][0] = s; g_part[blockIdx.x][1] = s2; }
    }
}

__global__ void finalize_k() {
    int lane = threadIdx.x;                 // 32 threads
    double s = 0.0, s2 = 0.0;
    for (int i = lane; i < RBLOCKS; i += 32) { s += g_part[i][0]; s2 += g_part[i][1]; }
    #pragma unroll
    for (int o = 16; o > 0; o >>= 1) {
        s  += __shfl_down_sync(0xffffffffu, s,  o);
        s2 += __shfl_down_sync(0xffffffffu, s2, o);
    }
    if (lane == 0) {
        double n = (double)(TRAIN - SPIN);
        g_obsstd = (float)sqrt((s2 - s * s / n) / (n - 1.0));
    }
}

// ---------------- kernel: transpose x[ch*64+s] -> xT[s][ch] --------------
// 32(chunk) x 32(step) float2 tiles, one per warp.
__global__ __launch_bounds__(128) void transpose_k(const float2* __restrict__ x) {
    __shared__ float2 tile[4][32][33];
    const int lane = threadIdx.x & 31;
    const int warp = threadIdx.x >> 5;
    const int gtile = blockIdx.x * 4 + warp;
    const int ntile_c = NCHPAD / 32;                 // 492
    const int tc = gtile % ntile_c;                  // chunk-tile
    const int ts = gtile / ntile_c;                  // step-tile (0..1)
    if (ts >= CHUNK / 32) return;
    const int c0 = tc * 32;
    const int s0 = ts * 32;
    #pragma unroll 4
    for (int i = 0; i < 32; ++i) {                   // read: steps contiguous
        int ch = c0 + i;
        float2 v = make_float2(0.f, 0.f);
        if (ch < NCH) v = x[ch * CHUNK + s0 + lane];
        tile[warp][i][lane] = v;
    }
    __syncwarp();
    #pragma unroll 4
    for (int s = 0; s < 32; ++s) {                   // write: chunks contiguous
        int ch = c0 + lane;
        g_xT[(s0 + s) * NCHPAD + ch] = tile[warp][lane][s];
    }
}

// ---------------- kernel: chunked scan (phase 1) --------------------------
// Thread = one 64-step chunk; warm-up replays the 2 previous chunks from c=0.
// Writes the pre-update state trajectory coalesced via SMEM transpose.
__global__ __launch_bounds__(SCAN_BLK) void scan_k(
    float* __restrict__ c_out,
    const float* cmean, const float* cstd,
    const float* wro, const float* wrl, const float* wrf,
    const float* b0o, const float* wb1o,
    const float* b0l, const float* wb2l,
    const float* wb1u, const float* b0u)
{
    __shared__ float tile[SCAN_BLK / 32][32][33];
    const int lane = threadIdx.x & 31;
    const int warp = threadIdx.x >> 5;
    const int chunk = blockIdx.x * SCAN_BLK + threadIdx.x;
    const bool act = (chunk < NCH);

    const P p = load_params(cmean, cstd, wro, wrl, wrf, b0o, wb1o, b0l, wb2l, wb1u, b0u);

    float c = 0.0f;
    if (act) {
        #pragma unroll
        for (int d = WARMCH; d >= 1; --d) {
            int j = chunk - d;
            if (j >= 0) {
                #pragma unroll 8
                for (int s = 0; s < CHUNK; ++s) {
                    float2 u = g_xT[s * NCHPAD + j];
                    c = step_c(c, u.x, u.y, p);
                }
            }
        }
    }

    const int w0 = blockIdx.x * SCAN_BLK + warp * 32;   // warp's first chunk
    #pragma unroll
    for (int half = 0; half < CHUNK / 32; ++half) {
        if (act) {
            #pragma unroll 8
            for (int s = 0; s < 32; ++s) {
                tile[warp][lane][s] = c;                 // state BEFORE update
                float2 u = g_xT[(half * 32 + s) * NCHPAD + chunk];
                c = step_c(c, u.x, u.y, p);
            }
        }
        __syncwarp();
        #pragma unroll 4
        for (int r = 0; r < 32; ++r) {
            int ch = w0 + r;
            if (ch < NCH)
                c_out[ch * CHUNK + half * 32 + lane] = tile[warp][r][lane];
        }
        __syncwarp();
    }
}

// ---------------- kernel: pointwise outputs (phase 2, 4-wide) -------------
__global__ __launch_bounds__(256) void point_k(
    const float4* __restrict__ x4,        // x as float4: 2 timesteps each
    float* __restrict__ out,
    const int* __restrict__ time_lag_p,
    const float* cmean, const float* cstd,
    const float* wro, const float* wrl, const float* wrf,
    const float* b0o, const float* wb1o,
    const float* b0l, const float* wb2l,
    const float* wb1u, const float* b0u)
{
    int i = blockIdx.x * blockDim.x + threadIdx.x;     // quad index
    if (i >= B_TOT / 4) return;

    const P p = load_params(cmean, cstd, wro, wrl, wrf, b0o, wb1o, b0l, wb2l, wb1u, b0u);
    const int   tl = time_lag_p[0];
    const float os = g_obsstd;
    const size_t B = (size_t)B_TOT;

    float4 c4 = reinterpret_cast<const float4*>(out + B)[i];
    float4 xa = x4[2 * i];
    float4 xb = x4[2 * i + 1];

    float cv[4]  = {c4.x, c4.y, c4.z, c4.w};
    float u1v[4] = {xa.x, xa.z, xb.x, xb.z};
    float u2v[4] = {xa.y, xa.w, xb.y, xb.w};

    float4 o_h, o_c, o_l, o_lc, o_bp, o_ib, o_oo, o_ol, o_olc, o_f;
    float  hs[4];
    float* oh = &o_h.x; float* oc = &o_c.x; float* olv = &o_l.x; float* olc4 = &o_lc.x;
    float* obp = &o_bp.x; float* oib = &o_ib.x; float* ooo = &o_oo.x;
    float* ool = &o_ol.x; float* oolc = &o_olc.x; float* of = &o_f.x;

    int t0 = 4 * i;
    #pragma unroll
    for (int j = 0; j < 4; ++j) {
        float c = cv[j], u1 = u1v[j], u2 = u2v[j];
        float zo = fmaf(c, p.koo, p.coo);
        float zi = fmaf(c, p.kib, fmaf(u1, p.kibu, p.cib));
        float zl = fmaf(u2, p.kol, p.col);
        float oo = fmaf(tanha(zo), p.hoo1, p.hoo1);
        float ib = fmaf(tanha(zi), 0.5f, 0.5f);
        float ol = fmaf(tanha(zl), p.hol1, p.hol1);
        float olc = (c > 0.0f) ? fminf(ol, __fdividef(u2, c)) : ol;
        float f   = 1.0f - oo - olc;
        float m   = (t0 + j >= tl) ? 1.0f : 0.0f;
        float bp  = ib * u1;
        float h   = fmaf(oo, c, bp);
        oh[j]   = m * h;
        oc[j]   = m * c;
        olv[j]  = m * (ol * c);
        olc4[j] = m * (olc * c);
        obp[j]  = m * bp;
        oib[j]  = m * ib;
        ooo[j]  = m * oo;
        ool[j]  = m * ol;
        oolc[j] = m * olc;
        of[j]   = m * f;
        hs[j]   = m * h;
    }
    float osm = ((t0 + 3) >= tl) ? os : 0.0f;          // per-element below if split
    // obs_std mask per element (handles tl falling inside the quad)
    float osv[4];
    #pragma unroll
    for (int j = 0; j < 4; ++j) osv[j] = (t0 + j >= tl) ? os : 0.0f;
    (void)osm;

    reinterpret_cast<float4*>(out)[i]          = o_h;
    reinterpret_cast<float4*>(out + B)[i]      = o_c;
    reinterpret_cast<float4*>(out + 2 * B)[i]  = o_l;
    reinterpret_cast<float4*>(out + 3 * B)[i]  = o_lc;
    reinterpret_cast<float4*>(out + 4 * B)[i]  = o_bp;
    reinterpret_cast<float4*>(out + 5 * B)[i]  = o_ib;
    reinterpret_cast<float4*>(out + 6 * B)[i]  = o_oo;
    reinterpret_cast<float4*>(out + 7 * B)[i]  = o_ol;
    reinterpret_cast<float4*>(out + 8 * B)[i]  = o_olc;
    reinterpret_cast<float4*>(out + 9 * B)[i]  = o_f;
    float4* hn4 = reinterpret_cast<float4*>(out + 10 * B);
    hn4[2 * i]     = make_float4(hs[0], osv[0], hs[1], osv[1]);
    hn4[2 * i + 1] = make_float4(hs[2], osv[2], hs[3], osv[3]);
    reinterpret_cast<float4*>(out + 12 * B)[i] =
        make_float4(osv[0], osv[1], osv[2], osv[3]);
}

// ---------------- launch ----------------
extern "C" void kernel_launch(void* const* d_in, const int* in_sizes, int n_in,
                              void* d_out, int out_size) {
    const float2* x     = (const float2*)d_in[0];
    const int*    tl    = (const int*)   d_in[2];
    const float*  y_obs = (const float*) d_in[3];
    const float*  cmean = (const float*) d_in[4];
    const float*  cstd  = (const float*) d_in[5];
    const float*  wro   = (const float*) d_in[6];
    const float*  wrl   = (const float*) d_in[7];
    const float*  wrf   = (const float*) d_in[8];
    const float*  b0o   = (const float*) d_in[9];
    const float*  wb1o  = (const float*) d_in[10];
    const float*  b0l   = (const float*) d_in[11];
    const float*  wb2l  = (const float*) d_in[12];
    const float*  wb1u  = (const float*) d_in[13];
    const float*  b0u   = (const float*) d_in[14];
    float* out = (float*)d_out;

    reduce_k<<<RBLOCKS, 256>>>(y_obs);
    finalize_k<<<1, 32>>>();

    constexpr int TT = (NCHPAD / 32) * (CHUNK / 32);      // 984 warp-tiles
    transpose_k<<<TT / 4, 128>>>(x);

    float* c_out = out + (size_t)B_TOT;                   // stash c in c_n slot
    scan_k<<<SCAN_GRID, SCAN_BLK>>>(c_out,
        cmean, cstd, wro, wrl, wrf, b0o, wb1o, b0l, wb2l, wb1u, b0u);

    point_k<<<(B_TOT / 4 + 255) / 256, 256>>>(
        (const float4*)x, out, tl,
        cmean, cstd, wro, wrl, wrf, b0o, wb1o, b0l, wb2l, wb1u, b0u);
}

// round 4
// speedup vs baseline: 4.2193x; 1.7845x over previous
#include <cuda_runtime.h>
#include <math.h>

// ---------------- problem constants ----------------
constexpr int   B_TOT  = 1000000;
constexpr int   SPIN   = 1000;
constexpr int   TRAIN  = 800000;
constexpr float ML     = 2.9086f;
constexpr float SL     = 1.898f;
constexpr float U1MAX  = 221.519f;

// chunked-scan parameters
constexpr int CHUNK   = 32;                   // steps per chunk
constexpr int WARMCH  = 2;                    // warm-up chunks (64 steps)
constexpr int NCH     = B_TOT / CHUNK;        // 31250 (exact)
constexpr int SBLK    = 128;                  // threads (=chunks) per block
constexpr int SGRID   = (NCH + SBLK - 1) / SBLK;   // 245

// ---------------- reduction scratch ----------------
constexpr int RBLOCKS = 132;
__device__ double g_part[RBLOCKS][2];
__device__ float  g_obsstd;

// ---------------- math helpers ----------------
__device__ __forceinline__ float tanha(float z) {
    float r;
    asm("tanh.approx.f32 %0, %1;" : "=f"(r) : "f"(z));
    return r;
}

struct P {
    float koo, coo;        // zo = koo*c + coo
    float kib, cib, kibu;  // zi = kib*c + (kibu*u1 + cib)
    float kol, col;        // zl = kol*u2 + col
    float hoo1, hol1;      // 0.5*oo1, 0.5*ol1
};

__device__ __forceinline__ P load_params(
    const float* cmean, const float* cstd,
    const float* wro, const float* wrl, const float* wrf,
    const float* b0o, const float* wb1o,
    const float* b0l, const float* wb2l,
    const float* wb1u, const float* b0u)
{
    P p;
    float mo = cmean[0];
    float inv_so = 1.0f / cstd[0];
    float eo = __expf(wro[0]);
    float el = __expf(wrl[0]);
    float ef = __expf(wrf[0]);
    float id = __fdividef(1.0f, eo + el + ef);
    p.hoo1 = 0.5f * eo * id;
    p.hol1 = 0.5f * el * id;
    float w1o = wb1o[0], w1u = wb1u[0], w2l = wb2l[0];
    p.koo  = 0.5f * w1o * inv_so;
    p.coo  = 0.5f * (b0o[0] - mo * inv_so * w1o);
    p.kib  = 0.5f * w1u * inv_so;
    p.cib  = 0.5f * (b0u[0] - mo * inv_so * w1u);
    p.kibu = 0.5f * w1u / U1MAX;
    p.kol  = 0.5f * w2l / SL;
    p.col  = 0.5f * (b0l[0] - (ML / SL) * w2l);
    return p;
}

// one recurrence step. sigmoid(z)=0.5*tanh(z/2)+0.5; min(ol,u2/c)*c == min(ol*c,u2).
// chain: fma -> tanh -> fma -> fma (~28 cyc); everything else off-chain.
__device__ __forceinline__ float step_c(float c, float u1, float u2, const P& p) {
    float hu1 = 0.5f * u1;                       // off-chain
    float zib = fmaf(u1, p.kibu, p.cib);         // off-chain
    float zl  = fmaf(u2, p.kol, p.col);          // off-chain
    float ol  = fmaf(tanha(zl), p.hol1, p.hol1); // off-chain MUFU
    float zo  = fmaf(c, p.koo, p.coo);
    float zi  = fmaf(c, p.kib, zib);
    float to  = tanha(zo);
    float ti  = tanha(zi);
    float hc  = p.hoo1 * c;                      // parallel with tanh
    float olc_c = ol * c;
    float L   = (c > 0.0f) ? fminf(olc_c, u2) : olc_c;
    float base = ((c - hc) + hu1) - L;           // parallel with tanh
    return fmaf(-hu1, ti, fmaf(-hc, to, base));
}

// ---------------- kernel: sum/sumsq partials over y_obs[SPIN:TRAIN] ------
__global__ __launch_bounds__(256) void reduce_k(const float* __restrict__ y) {
    const float4* y4 = reinterpret_cast<const float4*>(y + SPIN);
    const int n4 = (TRAIN - SPIN) / 4;
    double s = 0.0, s2 = 0.0;
    int stride = gridDim.x * blockDim.x;
    for (int i = blockIdx.x * blockDim.x + threadIdx.x; i < n4; i += stride) {
        float4 v = y4[i];
        double a = v.x, b = v.y, cc = v.z, d = v.w;
        s  += (a + b) + (cc + d);
        s2 += (a * a + b * b) + (cc * cc + d * d);
    }
    #pragma unroll
    for (int o = 16; o > 0; o >>= 1) {
        s  += __shfl_down_sync(0xffffffffu, s,  o);
        s2 += __shfl_down_sync(0xffffffffu, s2, o);
    }
    __shared__ double sh[2][8];
    int lane = threadIdx.x & 31, warp = threadIdx.x >> 5;
    if (lane == 0) { sh[0][warp] = s; sh[1][warp] = s2; }
    __syncthreads();
    if (warp == 0) {
        s  = (lane < 8) ? sh[0][lane] : 0.0;
        s2 = (lane < 8) ? sh[1][lane] : 0.0;
        #pragma unroll
        for (int o = 4; o > 0; o >>= 1) {
            s  += __shfl_down_sync(0xffffffffu, s,  o);
            s2 += __shfl_down_sync(0xffffffffu, s2, o);
        }
        if (lane == 0) { g_part[blockIdx.x][0] = s; g_part[blockIdx.x][1] = s2; }
    }
}

__global__ void finalize_k() {
    int lane = threadIdx.x;                 // 32 threads
    double s = 0.0, s2 = 0.0;
    for (int i = lane; i < RBLOCKS; i += 32) { s += g_part[i][0]; s2 += g_part[i][1]; }
    #pragma unroll
    for (int o = 16; o > 0; o >>= 1) {
        s  += __shfl_down_sync(0xffffffffu, s,  o);
        s2 += __shfl_down_sync(0xffffffffu, s2, o);
    }
    if (lane == 0) {
        double n = (double)(TRAIN - SPIN);
        g_obsstd = (float)sqrt((s2 - s * s / n) / (n - 1.0));
    }
}

// ---------------- kernel: chunked scan, SMEM-staged -----------------------
// Block b owns chunks [b0, b0+SBLK); its x-window (incl. WARMCH warm chunks)
// is the contiguous range [(b0-WARMCH)*32, (b0+SBLK)*32) — staged once into
// SMEM with coalesced float4 loads. The recurrence then touches only SMEM.
// The pre-update state overwrites .x of each consumed input slot; a final
// cooperative pass writes c_out coalesced.
__global__ __launch_bounds__(SBLK) void scan_k(
    const float4* __restrict__ x4,
    float* __restrict__ c_out,
    const float* cmean, const float* cstd,
    const float* wro, const float* wrl, const float* wrf,
    const float* b0o, const float* wb1o,
    const float* b0l, const float* wb2l,
    const float* wb1u, const float* b0u)
{
    __shared__ float2 sx[SBLK + WARMCH][CHUNK + 1];   // 130 x 33 float2 = 34.3KB

    const int tid = threadIdx.x;
    const int b0  = blockIdx.x * SBLK;                 // first owned chunk
    const int base_t = (b0 - WARMCH) * CHUNK;          // window start (may be <0)

    const P p = load_params(cmean, cstd, wro, wrl, wrf, b0o, wb1o, b0l, wb2l, wb1u, b0u);

    // ---- stage window: (SBLK+WARMCH)*CHUNK timesteps, 2 per float4 ----
    constexpr int NLD4 = (SBLK + WARMCH) * CHUNK / 2;  // 2080
    #pragma unroll 4
    for (int i = tid; i < NLD4; i += SBLK) {
        int t = base_t + 2 * i;
        float4 v = make_float4(0.f, 0.f, 0.f, 0.f);
        if (t >= 0 && t < B_TOT) v = __ldg(x4 + (t >> 1));
        int li = 2 * i;                                // local timestep
        int row = li >> 5, s = li & 31;
        sx[row][s]     = make_float2(v.x, v.y);
        sx[row][s + 1] = make_float2(v.z, v.w);
    }
    __syncthreads();

    // ---- recurrence ----
    const int chunk = b0 + tid;
    const int row   = tid + WARMCH;                    // own SMEM row
    float c = 0.0f;
    if (chunk < NCH) {
        #pragma unroll
        for (int d = WARMCH; d >= 1; --d) {
            if (chunk - d >= 0) {
                #pragma unroll 8
                for (int s = 0; s < CHUNK; ++s) {
                    float2 u = sx[row - d][s];
                    c = step_c(c, u.x, u.y, p);
                }
            }
        }
        #pragma unroll 8
        for (int s = 0; s < CHUNK; ++s) {
            float2 u = sx[row][s];
            sx[row][s].x = c;                          // record pre-update state
            c = step_c(c, u.x, u.y, p);
        }
    }
    __syncthreads();

    // ---- coalesced write-back of c trajectory ----
    const int t0 = b0 * CHUNK;
    #pragma unroll 4
    for (int i = tid; i < SBLK * CHUNK; i += SBLK) {
        int t = t0 + i;
        if (t < B_TOT) c_out[t] = sx[(i >> 5) + WARMCH][i & 31].x;
    }
}

// ---------------- kernel: pointwise outputs (phase 2, 4-wide) -------------
__global__ __launch_bounds__(256) void point_k(
    const float4* __restrict__ x4,        // x as float4: 2 timesteps each
    float* __restrict__ out,
    const int* __restrict__ time_lag_p,
    const float* cmean, const float* cstd,
    const float* wro, const float* wrl, const float* wrf,
    const float* b0o, const float* wb1o,
    const float* b0l, const float* wb2l,
    const float* wb1u, const float* b0u)
{
    int i = blockIdx.x * blockDim.x + threadIdx.x;     // quad index
    if (i >= B_TOT / 4) return;

    const P p = load_params(cmean, cstd, wro, wrl, wrf, b0o, wb1o, b0l, wb2l, wb1u, b0u);
    const int   tl = time_lag_p[0];
    const float os = g_obsstd;
    const size_t B = (size_t)B_TOT;

    float4 c4 = reinterpret_cast<const float4*>(out + B)[i];
    float4 xa = x4[2 * i];
    float4 xb = x4[2 * i + 1];

    float cv[4]  = {c4.x, c4.y, c4.z, c4.w};
    float u1v[4] = {xa.x, xa.z, xb.x, xb.z};
    float u2v[4] = {xa.y, xa.w, xb.y, xb.w};

    float4 o_h, o_c, o_l, o_lc, o_bp, o_ib, o_oo, o_ol, o_olc, o_f;
    float  hs[4], osv[4];
    float* oh = &o_h.x; float* oc = &o_c.x; float* olv = &o_l.x; float* olc4 = &o_lc.x;
    float* obp = &o_bp.x; float* oib = &o_ib.x; float* ooo = &o_oo.x;
    float* ool = &o_ol.x; float* oolc = &o_olc.x; float* of = &o_f.x;

    int t0 = 4 * i;
    #pragma unroll
    for (int j = 0; j < 4; ++j) {
        float c = cv[j], u1 = u1v[j], u2 = u2v[j];
        float zo = fmaf(c, p.koo, p.coo);
        float zi = fmaf(c, p.kib, fmaf(u1, p.kibu, p.cib));
        float zl = fmaf(u2, p.kol, p.col);
        float oo = fmaf(tanha(zo), p.hoo1, p.hoo1);
        float ib = fmaf(tanha(zi), 0.5f, 0.5f);
        float ol = fmaf(tanha(zl), p.hol1, p.hol1);
        float olc = (c > 0.0f) ? fminf(ol, __fdividef(u2, c)) : ol;
        float f   = 1.0f - oo - olc;
        float m   = (t0 + j >= tl) ? 1.0f : 0.0f;
        float bp  = ib * u1;
        float h   = fmaf(oo, c, bp);
        oh[j]   = m * h;
        oc[j]   = m * c;
        olv[j]  = m * (ol * c);
        olc4[j] = m * (olc * c);
        obp[j]  = m * bp;
        oib[j]  = m * ib;
        ooo[j]  = m * oo;
        ool[j]  = m * ol;
        oolc[j] = m * olc;
        of[j]   = m * f;
        hs[j]   = m * h;
        osv[j]  = m * os;
    }

    reinterpret_cast<float4*>(out)[i]          = o_h;
    reinterpret_cast<float4*>(out + B)[i]      = o_c;
    reinterpret_cast<float4*>(out + 2 * B)[i]  = o_l;
    reinterpret_cast<float4*>(out + 3 * B)[i]  = o_lc;
    reinterpret_cast<float4*>(out + 4 * B)[i]  = o_bp;
    reinterpret_cast<float4*>(out + 5 * B)[i]  = o_ib;
    reinterpret_cast<float4*>(out + 6 * B)[i]  = o_oo;
    reinterpret_cast<float4*>(out + 7 * B)[i]  = o_ol;
    reinterpret_cast<float4*>(out + 8 * B)[i]  = o_olc;
    reinterpret_cast<float4*>(out + 9 * B)[i]  = o_f;
    float4* hn4 = reinterpret_cast<float4*>(out + 10 * B);
    hn4[2 * i]     = make_float4(hs[0], osv[0], hs[1], osv[1]);
    hn4[2 * i + 1] = make_float4(hs[2], osv[2], hs[3], osv[3]);
    reinterpret_cast<float4*>(out + 12 * B)[i] =
        make_float4(osv[0], osv[1], osv[2], osv[3]);
}

// ---------------- launch ----------------
extern "C" void kernel_launch(void* const* d_in, const int* in_sizes, int n_in,
                              void* d_out, int out_size) {
    const float4* x4    = (const float4*)d_in[0];
    const int*    tl    = (const int*)   d_in[2];
    const float*  y_obs = (const float*) d_in[3];
    const float*  cmean = (const float*) d_in[4];
    const float*  cstd  = (const float*) d_in[5];
    const float*  wro   = (const float*) d_in[6];
    const float*  wrl   = (const float*) d_in[7];
    const float*  wrf   = (const float*) d_in[8];
    const float*  b0o   = (const float*) d_in[9];
    const float*  wb1o  = (const float*) d_in[10];
    const float*  b0l   = (const float*) d_in[11];
    const float*  wb2l  = (const float*) d_in[12];
    const float*  wb1u  = (const float*) d_in[13];
    const float*  b0u   = (const float*) d_in[14];
    float* out = (float*)d_out;

    reduce_k<<<RBLOCKS, 256>>>(y_obs);
    finalize_k<<<1, 32>>>();

    float* c_out = out + (size_t)B_TOT;                   // stash c in c_n slot
    scan_k<<<SGRID, SBLK>>>(x4, c_out,
        cmean, cstd, wro, wrl, wrf, b0o, wb1o, b0l, wb2l, wb1u, b0u);

    point_k<<<(B_TOT / 4 + 255) / 256, 256>>>(
        x4, out, tl,
        cmean, cstd, wro, wrl, wrf, b0o, wb1o, b0l, wb2l, wb1u, b0u);
}

// round 5
// speedup vs baseline: 4.6172x; 1.0943x over previous
#include <cuda_runtime.h>
#include <math.h>

// ---------------- problem constants ----------------
constexpr int   B_TOT  = 1000000;
constexpr int   SPIN   = 1000;
constexpr int   TRAIN  = 800000;
constexpr float ML     = 2.9086f;
constexpr float SL     = 1.898f;
constexpr float U1MAX  = 221.519f;

// chunked-scan parameters
constexpr int CHUNK   = 32;                   // steps per chunk
constexpr int WARMCH  = 2;                    // warm-up chunks (64 steps)
constexpr int NCH     = B_TOT / CHUNK;        // 31250 (exact)
constexpr int SBLK    = 128;                  // threads (=chunks) per scan block
constexpr int SGRID   = (NCH + SBLK - 1) / SBLK;   // 245

// reduction blocks appended to the scan grid
constexpr int RBLOCKS = 132;

__device__ double g_part[RBLOCKS][2];

// ---------------- math helpers ----------------
__device__ __forceinline__ float tanha(float z) {
    float r;
    asm("tanh.approx.f32 %0, %1;" : "=f"(r) : "f"(z));
    return r;
}

struct P {
    float koo, coo;        // zo = koo*c + coo
    float kib, cib, kibu;  // zi = kib*c + (kibu*u1 + cib)
    float kol, col;        // zl = kol*u2 + col
    float hoo1, hol1;      // 0.5*oo1, 0.5*ol1
};

__device__ __forceinline__ P load_params(
    const float* cmean, const float* cstd,
    const float* wro, const float* wrl, const float* wrf,
    const float* b0o, const float* wb1o,
    const float* b0l, const float* wb2l,
    const float* wb1u, const float* b0u)
{
    P p;
    float mo = cmean[0];
    float inv_so = 1.0f / cstd[0];
    float eo = __expf(wro[0]);
    float el = __expf(wrl[0]);
    float ef = __expf(wrf[0]);
    float id = __fdividef(1.0f, eo + el + ef);
    p.hoo1 = 0.5f * eo * id;
    p.hol1 = 0.5f * el * id;
    float w1o = wb1o[0], w1u = wb1u[0], w2l = wb2l[0];
    p.koo  = 0.5f * w1o * inv_so;
    p.coo  = 0.5f * (b0o[0] - mo * inv_so * w1o);
    p.kib  = 0.5f * w1u * inv_so;
    p.cib  = 0.5f * (b0u[0] - mo * inv_so * w1u);
    p.kibu = 0.5f * w1u / U1MAX;
    p.kol  = 0.5f * w2l / SL;
    p.col  = 0.5f * (b0l[0] - (ML / SL) * w2l);
    return p;
}

// one recurrence step. sigmoid(z)=0.5*tanh(z/2)+0.5; min(ol,u2/c)*c == min(ol*c,u2).
// chain: fma -> tanh -> fma -> fma (~28 cyc); everything else off-chain.
__device__ __forceinline__ float step_c(float c, float u1, float u2, const P& p) {
    float hu1 = 0.5f * u1;                       // off-chain
    float zib = fmaf(u1, p.kibu, p.cib);         // off-chain
    float zl  = fmaf(u2, p.kol, p.col);          // off-chain
    float ol  = fmaf(tanha(zl), p.hol1, p.hol1); // off-chain MUFU
    float zo  = fmaf(c, p.koo, p.coo);
    float zi  = fmaf(c, p.kib, zib);
    float to  = tanha(zo);
    float ti  = tanha(zi);
    float hc  = p.hoo1 * c;                      // parallel with tanh
    float olc_c = ol * c;
    float L   = (c > 0.0f) ? fminf(olc_c, u2) : olc_c;
    float base = ((c - hc) + hu1) - L;           // parallel with tanh
    return fmaf(-hu1, ti, fmaf(-hc, to, base));
}

// ---------------- kernel A: fused scan + reduction partials ---------------
// Blocks [0, SGRID): SMEM-staged chunked scan writing the c trajectory.
// Blocks [SGRID, SGRID+RBLOCKS): sum/sumsq partials over y_obs[SPIN:TRAIN].
__global__ __launch_bounds__(SBLK) void scanreduce_k(
    const float4* __restrict__ x4,
    float* __restrict__ c_out,
    const float* __restrict__ y_obs,
    const float* cmean, const float* cstd,
    const float* wro, const float* wrl, const float* wrf,
    const float* b0o, const float* wb1o,
    const float* b0l, const float* wb2l,
    const float* wb1u, const float* b0u)
{
    __shared__ float2 sx[SBLK + WARMCH][CHUNK + 1];   // 130 x 33 float2 = 34.3KB
    __shared__ double shred[2][SBLK / 32];

    const int tid = threadIdx.x;

    if (blockIdx.x >= SGRID) {
        // ---------------- reduction branch ----------------
        const int rbid = blockIdx.x - SGRID;
        const float4* y4 = reinterpret_cast<const float4*>(y_obs + SPIN);
        const int n4 = (TRAIN - SPIN) / 4;
        double s = 0.0, s2 = 0.0;
        int stride = RBLOCKS * SBLK;
        for (int i = rbid * SBLK + tid; i < n4; i += stride) {
            float4 v = __ldg(y4 + i);
            double a = v.x, b = v.y, cc = v.z, d = v.w;
            s  += (a + b) + (cc + d);
            s2 += (a * a + b * b) + (cc * cc + d * d);
        }
        #pragma unroll
        for (int o = 16; o > 0; o >>= 1) {
            s  += __shfl_down_sync(0xffffffffu, s,  o);
            s2 += __shfl_down_sync(0xffffffffu, s2, o);
        }
        int lane = tid & 31, warp = tid >> 5;
        if (lane == 0) { shred[0][warp] = s; shred[1][warp] = s2; }
        __syncthreads();
        if (warp == 0) {
            s  = (lane < SBLK / 32) ? shred[0][lane] : 0.0;
            s2 = (lane < SBLK / 32) ? shred[1][lane] : 0.0;
            #pragma unroll
            for (int o = 2; o > 0; o >>= 1) {
                s  += __shfl_down_sync(0xffffffffu, s,  o);
                s2 += __shfl_down_sync(0xffffffffu, s2, o);
            }
            if (lane == 0) { g_part[rbid][0] = s; g_part[rbid][1] = s2; }
        }
        return;
    }

    // ---------------- scan branch ----------------
    const int b0  = blockIdx.x * SBLK;                 // first owned chunk
    const int base_t = (b0 - WARMCH) * CHUNK;          // window start (may be <0)

    const P p = load_params(cmean, cstd, wro, wrl, wrf, b0o, wb1o, b0l, wb2l, wb1u, b0u);

    // stage window: (SBLK+WARMCH)*CHUNK timesteps, 2 per float4
    constexpr int NLD4 = (SBLK + WARMCH) * CHUNK / 2;  // 2080
    #pragma unroll 4
    for (int i = tid; i < NLD4; i += SBLK) {
        int t = base_t + 2 * i;
        float4 v = make_float4(0.f, 0.f, 0.f, 0.f);
        if (t >= 0 && t < B_TOT) v = __ldg(x4 + (t >> 1));
        int li = 2 * i;                                // local timestep
        int row = li >> 5, s = li & 31;
        sx[row][s]     = make_float2(v.x, v.y);
        sx[row][s + 1] = make_float2(v.z, v.w);
    }
    __syncthreads();

    // recurrence
    const int chunk = b0 + tid;
    const int row   = tid + WARMCH;                    // own SMEM row
    float c = 0.0f;
    if (chunk < NCH) {
        #pragma unroll
        for (int d = WARMCH; d >= 1; --d) {
            if (chunk - d >= 0) {
                #pragma unroll 8
                for (int s = 0; s < CHUNK; ++s) {
                    float2 u = sx[row - d][s];
                    c = step_c(c, u.x, u.y, p);
                }
            }
        }
        #pragma unroll 8
        for (int s = 0; s < CHUNK; ++s) {
            float2 u = sx[row][s];
            sx[row][s].x = c;                          // record pre-update state
            c = step_c(c, u.x, u.y, p);
        }
    }
    __syncthreads();

    // coalesced write-back of c trajectory
    const int t0 = b0 * CHUNK;
    #pragma unroll 4
    for (int i = tid; i < SBLK * CHUNK; i += SBLK) {
        int t = t0 + i;
        if (t < B_TOT) c_out[t] = sx[(i >> 5) + WARMCH][i & 31].x;
    }
}

// ---------------- kernel B: pointwise outputs + inline std finalize -------
__global__ __launch_bounds__(256) void point_k(
    const float4* __restrict__ x4,        // x as float4: 2 timesteps each
    float* __restrict__ out,
    const int* __restrict__ time_lag_p,
    const float* cmean, const float* cstd,
    const float* wro, const float* wrl, const float* wrf,
    const float* b0o, const float* wb1o,
    const float* b0l, const float* wb2l,
    const float* wb1u, const float* b0u)
{
    __shared__ float s_os;

    // warp 0: fold the RBLOCKS partials into obsstd (ddof=1)
    if (threadIdx.x < 32) {
        int lane = threadIdx.x;
        double s = 0.0, s2 = 0.0;
        for (int i = lane; i < RBLOCKS; i += 32) {
            s  += g_part[i][0];
            s2 += g_part[i][1];
        }
        #pragma unroll
        for (int o = 16; o > 0; o >>= 1) {
            s  += __shfl_down_sync(0xffffffffu, s,  o);
            s2 += __shfl_down_sync(0xffffffffu, s2, o);
        }
        if (lane == 0) {
            double n = (double)(TRAIN - SPIN);
            s_os = (float)sqrt((s2 - s * s / n) / (n - 1.0));
        }
    }

    int i = blockIdx.x * blockDim.x + threadIdx.x;     // quad index
    bool act = (i < B_TOT / 4);

    const P p = load_params(cmean, cstd, wro, wrl, wrf, b0o, wb1o, b0l, wb2l, wb1u, b0u);
    const int tl = time_lag_p[0];
    const size_t B = (size_t)B_TOT;

    float4 c4 = make_float4(0.f, 0.f, 0.f, 0.f);
    float4 xa = c4, xb = c4;
    if (act) {
        c4 = reinterpret_cast<const float4*>(out + B)[i];
        xa = x4[2 * i];
        xb = x4[2 * i + 1];
    }

    __syncthreads();
    const float os = s_os;
    if (!act) return;

    float cv[4]  = {c4.x, c4.y, c4.z, c4.w};
    float u1v[4] = {xa.x, xa.z, xb.x, xb.z};
    float u2v[4] = {xa.y, xa.w, xb.y, xb.w};

    float4 o_h, o_c, o_l, o_lc, o_bp, o_ib, o_oo, o_ol, o_olc, o_f;
    float  hs[4], osv[4];
    float* oh = &o_h.x; float* oc = &o_c.x; float* olv = &o_l.x; float* olc4 = &o_lc.x;
    float* obp = &o_bp.x; float* oib = &o_ib.x; float* ooo = &o_oo.x;
    float* ool = &o_ol.x; float* oolc = &o_olc.x; float* of = &o_f.x;

    int t0 = 4 * i;
    #pragma unroll
    for (int j = 0; j < 4; ++j) {
        float c = cv[j], u1 = u1v[j], u2 = u2v[j];
        float zo = fmaf(c, p.koo, p.coo);
        float zi = fmaf(c, p.kib, fmaf(u1, p.kibu, p.cib));
        float zl = fmaf(u2, p.kol, p.col);
        float oo = fmaf(tanha(zo), p.hoo1, p.hoo1);
        float ib = fmaf(tanha(zi), 0.5f, 0.5f);
        float ol = fmaf(tanha(zl), p.hol1, p.hol1);
        float olc = (c > 0.0f) ? fminf(ol, __fdividef(u2, c)) : ol;
        float f   = 1.0f - oo - olc;
        float m   = (t0 + j >= tl) ? 1.0f : 0.0f;
        float bp  = ib * u1;
        float h   = fmaf(oo, c, bp);
        oh[j]   = m * h;
        oc[j]   = m * c;
        olv[j]  = m * (ol * c);
        olc4[j] = m * (olc * c);
        obp[j]  = m * bp;
        oib[j]  = m * ib;
        ooo[j]  = m * oo;
        ool[j]  = m * ol;
        oolc[j] = m * olc;
        of[j]   = m * f;
        hs[j]   = m * h;
        osv[j]  = m * os;
    }

    reinterpret_cast<float4*>(out)[i]          = o_h;
    reinterpret_cast<float4*>(out + B)[i]      = o_c;
    reinterpret_cast<float4*>(out + 2 * B)[i]  = o_l;
    reinterpret_cast<float4*>(out + 3 * B)[i]  = o_lc;
    reinterpret_cast<float4*>(out + 4 * B)[i]  = o_bp;
    reinterpret_cast<float4*>(out + 5 * B)[i]  = o_ib;
    reinterpret_cast<float4*>(out + 6 * B)[i]  = o_oo;
    reinterpret_cast<float4*>(out + 7 * B)[i]  = o_ol;
    reinterpret_cast<float4*>(out + 8 * B)[i]  = o_olc;
    reinterpret_cast<float4*>(out + 9 * B)[i]  = o_f;
    float4* hn4 = reinterpret_cast<float4*>(out + 10 * B);
    hn4[2 * i]     = make_float4(hs[0], osv[0], hs[1], osv[1]);
    hn4[2 * i + 1] = make_float4(hs[2], osv[2], hs[3], osv[3]);
    reinterpret_cast<float4*>(out + 12 * B)[i] =
        make_float4(osv[0], osv[1], osv[2], osv[3]);
}

// ---------------- launch ----------------
extern "C" void kernel_launch(void* const* d_in, const int* in_sizes, int n_in,
                              void* d_out, int out_size) {
    const float4* x4    = (const float4*)d_in[0];
    const int*    tl    = (const int*)   d_in[2];
    const float*  y_obs = (const float*) d_in[3];
    const float*  cmean = (const float*) d_in[4];
    const float*  cstd  = (const float*) d_in[5];
    const float*  wro   = (const float*) d_in[6];
    const float*  wrl   = (const float*) d_in[7];
    const float*  wrf   = (const float*) d_in[8];
    const float*  b0o   = (const float*) d_in[9];
    const float*  wb1o  = (const float*) d_in[10];
    const float*  b0l   = (const float*) d_in[11];
    const float*  wb2l  = (const float*) d_in[12];
    const float*  wb1u  = (const float*) d_in[13];
    const float*  b0u   = (const float*) d_in[14];
    float* out = (float*)d_out;

    float* c_out = out + (size_t)B_TOT;                   // stash c in c_n slot
    scanreduce_k<<<SGRID + RBLOCKS, SBLK>>>(x4, c_out, y_obs,
        cmean, cstd, wro, wrl, wrf, b0o, wb1o, b0l, wb2l, wb1u, b0u);

    point_k<<<(B_TOT / 4 + 255) / 256, 256>>>(
        x4, out, tl,
        cmean, cstd, wro, wrl, wrf, b0o, wb1o, b0l, wb2l, wb1u, b0u);
}